// round 1
// baseline (speedup 1.0000x reference)
#include <cuda_runtime.h>
#include <math.h>

// Problem constants
#define BB   8
#define SS   1024
#define DD   1024
#define HH   8
#define DB   128
#define BH   64        // BB*HH
#define MTOT 8192      // BB*SS

// Scratch (device globals; allocation-free rule)
__device__ float g_vh[(size_t)BH * SS * DB];   // [b,h,s,d]
__device__ float g_kh[(size_t)BH * SS * DB];
__device__ float g_qh[(size_t)BH * SS * DB];
__device__ float g_gx[(size_t)BH * SS * DB];
__device__ float g_gy[(size_t)BH * SS * DB];
__device__ float g_sc[(size_t)BH * SS * SS];   // scores [bh, i, j]
__device__ float g_ctx[(size_t)MTOT * DD];     // merged-head context [b*s, d]

// ---------------------------------------------------------------------------
// 128x128 tile fp32 GEMM engine: BK=16, 256 threads, 8x8 per-thread microtile.
// BT=false: C = A(MxK) * B(KxN), both row-major.
// BT=true : C = A(MxK) * B(NxK)^T (both row-major) -- used for Q*K^T.
// M tile and N tile are always exactly 128; K multiple of 16. No bounds checks.
// ---------------------------------------------------------------------------
template<bool BT>
__device__ __forceinline__ void gemm_128x128(
    const float* __restrict__ A, int lda,
    const float* __restrict__ Bp, int ldb,
    int K,
    float (&As)[16][132], float (&Bs)[16][132],
    float (&acc)[8][8])
{
    const int t  = threadIdx.x;
    const int ty = t >> 4;
    const int tx = t & 15;
    for (int k0 = 0; k0 < K; k0 += 16) {
        // Load A tile 128x16, store transposed As[k][m]
#pragma unroll
        for (int r = 0; r < 2; r++) {
            int idx = t + r * 256;
            int row = idx >> 2;
            int qq  = (idx & 3) * 4;
            float4 av = *(const float4*)(A + (size_t)row * lda + k0 + qq);
            As[qq + 0][row] = av.x; As[qq + 1][row] = av.y;
            As[qq + 2][row] = av.z; As[qq + 3][row] = av.w;
        }
        if (!BT) {
            // Load B tile 16x128 directly: Bs[k][n]
#pragma unroll
            for (int r = 0; r < 2; r++) {
                int idx = t + r * 256;
                int kr  = idx >> 5;
                int col = (idx & 31) * 4;
                *(float4*)&Bs[kr][col] =
                    *(const float4*)(Bp + (size_t)(k0 + kr) * ldb + col);
            }
        } else {
            // B is (N x K) row-major; gather Bs[k][n] = B[n][k]
#pragma unroll
            for (int r = 0; r < 2; r++) {
                int idx = t + r * 256;
                int row = idx >> 2;           // n index
                int qq  = (idx & 3) * 4;
                float4 bv = *(const float4*)(Bp + (size_t)row * ldb + k0 + qq);
                Bs[qq + 0][row] = bv.x; Bs[qq + 1][row] = bv.y;
                Bs[qq + 2][row] = bv.z; Bs[qq + 3][row] = bv.w;
            }
        }
        __syncthreads();
#pragma unroll
        for (int kk = 0; kk < 16; kk++) {
            float a[8], b[8];
            *(float4*)&a[0] = *(const float4*)&As[kk][ty * 8];
            *(float4*)&a[4] = *(const float4*)&As[kk][ty * 8 + 4];
            *(float4*)&b[0] = *(const float4*)&Bs[kk][tx * 8];
            *(float4*)&b[4] = *(const float4*)&Bs[kk][tx * 8 + 4];
#pragma unroll
            for (int i = 0; i < 8; i++)
#pragma unroll
                for (int j = 0; j < 8; j++)
                    acc[i][j] = fmaf(a[i], b[j], acc[i][j]);
        }
        __syncthreads();
    }
}

// ---------------------------------------------------------------------------
// K1: QKV projection. grid (64, 8, 3). z selects v/k/q.
// Writes directly into head-split layout [b,h,s,d].
// ---------------------------------------------------------------------------
__global__ __launch_bounds__(256)
void proj_kernel(const float* __restrict__ v, const float* __restrict__ k,
                 const float* __restrict__ q,
                 const float* __restrict__ Wv, const float* __restrict__ bv,
                 const float* __restrict__ Wk, const float* __restrict__ bk,
                 const float* __restrict__ Wq, const float* __restrict__ bq)
{
    __shared__ float As[16][132];
    __shared__ float Bs[16][132];
    float acc[8][8] = {};

    const float* A; const float* W; const float* bias; float* outp;
    if (blockIdx.z == 0)      { A = v; W = Wv; bias = bv; outp = g_vh; }
    else if (blockIdx.z == 1) { A = k; W = Wk; bias = bk; outp = g_kh; }
    else                      { A = q; W = Wq; bias = bq; outp = g_qh; }

    const int m0 = blockIdx.x * 128;
    const int n0 = blockIdx.y * 128;
    gemm_128x128<false>(A + (size_t)m0 * DD, DD, W + n0, DD, DD, As, Bs, acc);

    const int ty = threadIdx.x >> 4, tx = threadIdx.x & 15;
#pragma unroll
    for (int i = 0; i < 8; i++) {
        int m = m0 + ty * 8 + i;
        int b = m >> 10, s = m & 1023;
#pragma unroll
        for (int j = 0; j < 8; j++) {
            int n = n0 + tx * 8 + j;
            int h = n >> 7, d = n & 127;
            outp[(((size_t)(b * HH + h)) * SS + s) * DB + d] = acc[i][j] + bias[n];
        }
    }
}

// ---------------------------------------------------------------------------
// K2: gate projections gX = kh@WgX+bgX, gY = qh@WgY+bgY.
// grid (8, 2, 64): x = s-tile, y = which (0:gX 1:gY), z = bh.
// ---------------------------------------------------------------------------
__global__ __launch_bounds__(256)
void gate_gemm_kernel(const float* __restrict__ WgX, const float* __restrict__ bgX,
                      const float* __restrict__ WgY, const float* __restrict__ bgY)
{
    __shared__ float As[16][132];
    __shared__ float Bs[16][132];
    float acc[8][8] = {};

    const int bh  = blockIdx.z;
    const int sel = blockIdx.y;
    const size_t head_off = (size_t)bh * SS * DB;
    const float* A    = (sel ? g_qh : g_kh) + head_off + (size_t)blockIdx.x * 128 * DB;
    const float* W    = sel ? WgY : WgX;
    const float* bias = sel ? bgY : bgX;
    float* outp       = (sel ? g_gy : g_gx) + head_off + (size_t)blockIdx.x * 128 * DB;

    gemm_128x128<false>(A, DB, W, DB, DB, As, Bs, acc);

    const int ty = threadIdx.x >> 4, tx = threadIdx.x & 15;
#pragma unroll
    for (int i = 0; i < 8; i++)
#pragma unroll
        for (int j = 0; j < 8; j++) {
            int n = tx * 8 + j;
            outp[(size_t)(ty * 8 + i) * DB + n] = acc[i][j] + bias[n];
        }
}

// ---------------------------------------------------------------------------
// K3: gate apply. One row (b,h,s) per block of 128 threads.
// g0,g1 = sigmoid((gX*gY) @ Wg2 + bg2); kh *= g0; qh *= g1.
// ---------------------------------------------------------------------------
__global__ __launch_bounds__(128)
void gate_apply_kernel(const float* __restrict__ Wg2, const float* __restrict__ bg2)
{
    const int row = blockIdx.x;
    const int d   = threadIdx.x;
    const size_t o = (size_t)row * DB + d;

    float tv = g_gx[o] * g_gy[o];
    float s0 = tv * Wg2[d * 2 + 0];
    float s1 = tv * Wg2[d * 2 + 1];

    const int lane = d & 31, wid = d >> 5;
#pragma unroll
    for (int off = 16; off; off >>= 1) {
        s0 += __shfl_xor_sync(0xFFFFFFFFu, s0, off);
        s1 += __shfl_xor_sync(0xFFFFFFFFu, s1, off);
    }
    __shared__ float r0[4], r1[4];
    if (lane == 0) { r0[wid] = s0; r1[wid] = s1; }
    __syncthreads();
    float t0 = r0[0] + r0[1] + r0[2] + r0[3];
    float t1 = r1[0] + r1[1] + r1[2] + r1[3];
    float gk = 1.0f / (1.0f + expf(-(t0 + bg2[0])));
    float gq = 1.0f / (1.0f + expf(-(t1 + bg2[1])));
    g_kh[o] *= gk;
    g_qh[o] *= gq;
}

// ---------------------------------------------------------------------------
// K4: scores = (qh @ kh^T) / sqrt(DB), masked. grid (8, 8, 64).
// ---------------------------------------------------------------------------
__global__ __launch_bounds__(256)
void scores_kernel(const unsigned char* __restrict__ mask)
{
    __shared__ float As[16][132];
    __shared__ float Bs[16][132];
    float acc[8][8] = {};

    const int bh = blockIdx.z;
    const size_t head_off = (size_t)bh * SS * DB;
    const float* A  = g_qh + head_off + (size_t)blockIdx.x * 128 * DB;
    const float* Bp = g_kh + head_off + (size_t)blockIdx.y * 128 * DB;

    gemm_128x128<true>(A, DB, Bp, DB, DB, As, Bs, acc);

    const int ty = threadIdx.x >> 4, tx = threadIdx.x & 15;
    const int b  = bh >> 3;
    const float scale = 0.08838834764831845f;   // 1/sqrt(128)
    float* outp = g_sc + (size_t)bh * SS * SS;
#pragma unroll
    for (int i = 0; i < 8; i++) {
        int ii = blockIdx.x * 128 + ty * 8 + i;
#pragma unroll
        for (int j = 0; j < 8; j++) {
            int jj = blockIdx.y * 128 + tx * 8 + j;
            float val = acc[i][j] * scale;
            if (mask[b * SS + jj]) val = -1e9f;
            outp[(size_t)ii * SS + jj] = val;
        }
    }
}

// ---------------------------------------------------------------------------
// K5: row softmax over 1024 scores. 256 threads, 4 elements each (float4).
// ---------------------------------------------------------------------------
__global__ __launch_bounds__(256)
void softmax_kernel()
{
    const size_t row = blockIdx.x;
    float4* p = (float4*)(g_sc + row * SS);
    float4 vv = p[threadIdx.x];

    float m = fmaxf(fmaxf(vv.x, vv.y), fmaxf(vv.z, vv.w));
    const int lane = threadIdx.x & 31, wid = threadIdx.x >> 5;
#pragma unroll
    for (int off = 16; off; off >>= 1)
        m = fmaxf(m, __shfl_xor_sync(0xFFFFFFFFu, m, off));
    __shared__ float sm[8];
    if (lane == 0) sm[wid] = m;
    __syncthreads();
    m = sm[0];
#pragma unroll
    for (int w = 1; w < 8; w++) m = fmaxf(m, sm[w]);

    float4 e;
    e.x = __expf(vv.x - m); e.y = __expf(vv.y - m);
    e.z = __expf(vv.z - m); e.w = __expf(vv.w - m);
    float s = e.x + e.y + e.z + e.w;
#pragma unroll
    for (int off = 16; off; off >>= 1)
        s += __shfl_xor_sync(0xFFFFFFFFu, s, off);
    __shared__ float ss[8];
    if (lane == 0) ss[wid] = s;
    __syncthreads();
    s = ss[0] + ss[1] + ss[2] + ss[3] + ss[4] + ss[5] + ss[6] + ss[7];
    float inv = 1.0f / s;
    e.x *= inv; e.y *= inv; e.z *= inv; e.w *= inv;
    p[threadIdx.x] = e;
}

// ---------------------------------------------------------------------------
// K6: ctx = att @ vh, written into merged-head layout [b*s, h*128+d].
// grid (8, 1, 64).
// ---------------------------------------------------------------------------
__global__ __launch_bounds__(256)
void out_kernel()
{
    __shared__ float As[16][132];
    __shared__ float Bs[16][132];
    float acc[8][8] = {};

    const int bh = blockIdx.z;
    const int m0 = blockIdx.x * 128;
    const float* A  = g_sc + (size_t)bh * SS * SS + (size_t)m0 * SS;
    const float* Bp = g_vh + (size_t)bh * SS * DB;

    gemm_128x128<false>(A, SS, Bp, DB, SS, As, Bs, acc);

    const int ty = threadIdx.x >> 4, tx = threadIdx.x & 15;
    const int b = bh >> 3, h = bh & 7;
#pragma unroll
    for (int i = 0; i < 8; i++) {
        int s = m0 + ty * 8 + i;
#pragma unroll
        for (int j = 0; j < 8; j++) {
            int d = tx * 8 + j;
            g_ctx[((size_t)(b * SS + s)) * DD + h * DB + d] = acc[i][j];
        }
    }
}

// ---------------------------------------------------------------------------
// K7: final projection: out = ctx @ Wm + bm. grid (64, 8).
// ---------------------------------------------------------------------------
__global__ __launch_bounds__(256)
void final_kernel(const float* __restrict__ Wm, const float* __restrict__ bm,
                  float* __restrict__ outp)
{
    __shared__ float As[16][132];
    __shared__ float Bs[16][132];
    float acc[8][8] = {};

    const int m0 = blockIdx.x * 128;
    const int n0 = blockIdx.y * 128;
    gemm_128x128<false>(g_ctx + (size_t)m0 * DD, DD, Wm + n0, DD, DD, As, Bs, acc);

    const int ty = threadIdx.x >> 4, tx = threadIdx.x & 15;
#pragma unroll
    for (int i = 0; i < 8; i++) {
        int m = m0 + ty * 8 + i;
#pragma unroll
        for (int j = 0; j < 8; j++) {
            int n = n0 + tx * 8 + j;
            outp[(size_t)m * DD + n] = acc[i][j] + bm[n];
        }
    }
}

// ---------------------------------------------------------------------------
extern "C" void kernel_launch(void* const* d_in, const int* in_sizes, int n_in,
                              void* d_out, int out_size)
{
    (void)in_sizes; (void)n_in; (void)out_size;
    const float* v  = (const float*)d_in[0];
    const float* k  = (const float*)d_in[1];
    const float* q  = (const float*)d_in[2];
    const unsigned char* mask = (const unsigned char*)d_in[3];
    const float* Wv = (const float*)d_in[4];
    const float* bv = (const float*)d_in[5];
    const float* Wk = (const float*)d_in[6];
    const float* bk = (const float*)d_in[7];
    const float* Wq = (const float*)d_in[8];
    const float* bq = (const float*)d_in[9];
    const float* Wm = (const float*)d_in[10];
    const float* bm = (const float*)d_in[11];
    const float* WgX = (const float*)d_in[12];
    const float* bgX = (const float*)d_in[13];
    const float* WgY = (const float*)d_in[14];
    const float* bgY = (const float*)d_in[15];
    const float* Wg2 = (const float*)d_in[16];
    const float* bg2 = (const float*)d_in[17];
    float* outp = (float*)d_out;

    proj_kernel<<<dim3(64, 8, 3), 256>>>(v, k, q, Wv, bv, Wk, bk, Wq, bq);
    gate_gemm_kernel<<<dim3(8, 2, 64), 256>>>(WgX, bgX, WgY, bgY);
    gate_apply_kernel<<<BH * SS, 128>>>(Wg2, bg2);
    scores_kernel<<<dim3(8, 8, 64), 256>>>(mask);
    softmax_kernel<<<BH * SS, 256>>>();
    out_kernel<<<dim3(8, 1, 64), 256>>>();
    final_kernel<<<dim3(64, 8), 256>>>(Wm, bm, outp);
}

// round 2
// speedup vs baseline: 1.0002x; 1.0002x over previous
#include <cuda_runtime.h>
#include <math.h>

// Problem constants
#define BB   8
#define SS   1024
#define DD   1024
#define HH   8
#define DB   128
#define BH   64        // BB*HH
#define MTOT 8192      // BB*SS

// Scratch (device globals; allocation-free rule)
__device__ float g_vh[(size_t)BH * SS * DB];   // [b,h,s,d]
__device__ float g_kh[(size_t)BH * SS * DB];
__device__ float g_qh[(size_t)BH * SS * DB];
__device__ float g_gx[(size_t)BH * SS * DB];
__device__ float g_gy[(size_t)BH * SS * DB];
__device__ float g_sc[(size_t)BH * SS * SS];   // scores [bh, i, j]
__device__ float g_ctx[(size_t)MTOT * DD];     // merged-head context [b*s, d]

// ---------------------------------------------------------------------------
// 128x128 tile fp32 GEMM engine: BK=16, 256 threads, 8x8 per-thread microtile.
// BT=false: C = A(MxK) * B(KxN), both row-major.
// BT=true : C = A(MxK) * B(NxK)^T (both row-major) -- used for Q*K^T.
// M tile and N tile are always exactly 128; K multiple of 16. No bounds checks.
// ---------------------------------------------------------------------------
template<bool BT>
__device__ __forceinline__ void gemm_128x128(
    const float* __restrict__ A, int lda,
    const float* __restrict__ Bp, int ldb,
    int K,
    float (&As)[16][132], float (&Bs)[16][132],
    float (&acc)[8][8])
{
    const int t  = threadIdx.x;
    const int ty = t >> 4;
    const int tx = t & 15;
    for (int k0 = 0; k0 < K; k0 += 16) {
        // Load A tile 128x16, store transposed As[k][m]
#pragma unroll
        for (int r = 0; r < 2; r++) {
            int idx = t + r * 256;
            int row = idx >> 2;
            int qq  = (idx & 3) * 4;
            float4 av = *(const float4*)(A + (size_t)row * lda + k0 + qq);
            As[qq + 0][row] = av.x; As[qq + 1][row] = av.y;
            As[qq + 2][row] = av.z; As[qq + 3][row] = av.w;
        }
        if (!BT) {
            // Load B tile 16x128 directly: Bs[k][n]
#pragma unroll
            for (int r = 0; r < 2; r++) {
                int idx = t + r * 256;
                int kr  = idx >> 5;
                int col = (idx & 31) * 4;
                *(float4*)&Bs[kr][col] =
                    *(const float4*)(Bp + (size_t)(k0 + kr) * ldb + col);
            }
        } else {
            // B is (N x K) row-major; gather Bs[k][n] = B[n][k]
#pragma unroll
            for (int r = 0; r < 2; r++) {
                int idx = t + r * 256;
                int row = idx >> 2;           // n index
                int qq  = (idx & 3) * 4;
                float4 bv = *(const float4*)(Bp + (size_t)row * ldb + k0 + qq);
                Bs[qq + 0][row] = bv.x; Bs[qq + 1][row] = bv.y;
                Bs[qq + 2][row] = bv.z; Bs[qq + 3][row] = bv.w;
            }
        }
        __syncthreads();
#pragma unroll
        for (int kk = 0; kk < 16; kk++) {
            float a[8], b[8];
            *(float4*)&a[0] = *(const float4*)&As[kk][ty * 8];
            *(float4*)&a[4] = *(const float4*)&As[kk][ty * 8 + 4];
            *(float4*)&b[0] = *(const float4*)&Bs[kk][tx * 8];
            *(float4*)&b[4] = *(const float4*)&Bs[kk][tx * 8 + 4];
#pragma unroll
            for (int i = 0; i < 8; i++)
#pragma unroll
                for (int j = 0; j < 8; j++)
                    acc[i][j] = fmaf(a[i], b[j], acc[i][j]);
        }
        __syncthreads();
    }
}

// ---------------------------------------------------------------------------
// K1: QKV projection. grid (64, 8, 3). z selects v/k/q.
// Writes directly into head-split layout [b,h,s,d].
// ---------------------------------------------------------------------------
__global__ __launch_bounds__(256)
void proj_kernel(const float* __restrict__ v, const float* __restrict__ k,
                 const float* __restrict__ q,
                 const float* __restrict__ Wv, const float* __restrict__ bv,
                 const float* __restrict__ Wk, const float* __restrict__ bk,
                 const float* __restrict__ Wq, const float* __restrict__ bq)
{
    __shared__ float As[16][132];
    __shared__ float Bs[16][132];
    float acc[8][8] = {};

    const float* A; const float* W; const float* bias; float* outp;
    if (blockIdx.z == 0)      { A = v; W = Wv; bias = bv; outp = g_vh; }
    else if (blockIdx.z == 1) { A = k; W = Wk; bias = bk; outp = g_kh; }
    else                      { A = q; W = Wq; bias = bq; outp = g_qh; }

    const int m0 = blockIdx.x * 128;
    const int n0 = blockIdx.y * 128;
    gemm_128x128<false>(A + (size_t)m0 * DD, DD, W + n0, DD, DD, As, Bs, acc);

    const int ty = threadIdx.x >> 4, tx = threadIdx.x & 15;
#pragma unroll
    for (int i = 0; i < 8; i++) {
        int m = m0 + ty * 8 + i;
        int b = m >> 10, s = m & 1023;
#pragma unroll
        for (int j = 0; j < 8; j++) {
            int n = n0 + tx * 8 + j;
            int h = n >> 7, d = n & 127;
            outp[(((size_t)(b * HH + h)) * SS + s) * DB + d] = acc[i][j] + bias[n];
        }
    }
}

// ---------------------------------------------------------------------------
// K2: gate projections gX = kh@WgX+bgX, gY = qh@WgY+bgY.
// grid (8, 2, 64): x = s-tile, y = which (0:gX 1:gY), z = bh.
// ---------------------------------------------------------------------------
__global__ __launch_bounds__(256)
void gate_gemm_kernel(const float* __restrict__ WgX, const float* __restrict__ bgX,
                      const float* __restrict__ WgY, const float* __restrict__ bgY)
{
    __shared__ float As[16][132];
    __shared__ float Bs[16][132];
    float acc[8][8] = {};

    const int bh  = blockIdx.z;
    const int sel = blockIdx.y;
    const size_t head_off = (size_t)bh * SS * DB;
    const float* A    = (sel ? g_qh : g_kh) + head_off + (size_t)blockIdx.x * 128 * DB;
    const float* W    = sel ? WgY : WgX;
    const float* bias = sel ? bgY : bgX;
    float* outp       = (sel ? g_gy : g_gx) + head_off + (size_t)blockIdx.x * 128 * DB;

    gemm_128x128<false>(A, DB, W, DB, DB, As, Bs, acc);

    const int ty = threadIdx.x >> 4, tx = threadIdx.x & 15;
#pragma unroll
    for (int i = 0; i < 8; i++)
#pragma unroll
        for (int j = 0; j < 8; j++) {
            int n = tx * 8 + j;
            outp[(size_t)(ty * 8 + i) * DB + n] = acc[i][j] + bias[n];
        }
}

// ---------------------------------------------------------------------------
// K3: gate apply. One row (b,h,s) per block of 128 threads.
// g0,g1 = sigmoid((gX*gY) @ Wg2 + bg2); kh *= g0; qh *= g1.
// ---------------------------------------------------------------------------
__global__ __launch_bounds__(128)
void gate_apply_kernel(const float* __restrict__ Wg2, const float* __restrict__ bg2)
{
    const int row = blockIdx.x;
    const int d   = threadIdx.x;
    const size_t o = (size_t)row * DB + d;

    float tv = g_gx[o] * g_gy[o];
    float s0 = tv * Wg2[d * 2 + 0];
    float s1 = tv * Wg2[d * 2 + 1];

    const int lane = d & 31, wid = d >> 5;
#pragma unroll
    for (int off = 16; off; off >>= 1) {
        s0 += __shfl_xor_sync(0xFFFFFFFFu, s0, off);
        s1 += __shfl_xor_sync(0xFFFFFFFFu, s1, off);
    }
    __shared__ float r0[4], r1[4];
    if (lane == 0) { r0[wid] = s0; r1[wid] = s1; }
    __syncthreads();
    float t0 = r0[0] + r0[1] + r0[2] + r0[3];
    float t1 = r1[0] + r1[1] + r1[2] + r1[3];
    float gk = 1.0f / (1.0f + expf(-(t0 + bg2[0])));
    float gq = 1.0f / (1.0f + expf(-(t1 + bg2[1])));
    g_kh[o] *= gk;
    g_qh[o] *= gq;
}

// ---------------------------------------------------------------------------
// K4: scores = (qh @ kh^T) / sqrt(DB), masked. grid (8, 8, 64).
// ---------------------------------------------------------------------------
__global__ __launch_bounds__(256)
void scores_kernel(const unsigned char* __restrict__ mask)
{
    __shared__ float As[16][132];
    __shared__ float Bs[16][132];
    float acc[8][8] = {};

    const int bh = blockIdx.z;
    const size_t head_off = (size_t)bh * SS * DB;
    const float* A  = g_qh + head_off + (size_t)blockIdx.x * 128 * DB;
    const float* Bp = g_kh + head_off + (size_t)blockIdx.y * 128 * DB;

    gemm_128x128<true>(A, DB, Bp, DB, DB, As, Bs, acc);

    const int ty = threadIdx.x >> 4, tx = threadIdx.x & 15;
    const int b  = bh >> 3;
    const float scale = 0.08838834764831845f;   // 1/sqrt(128)
    float* outp = g_sc + (size_t)bh * SS * SS;
#pragma unroll
    for (int i = 0; i < 8; i++) {
        int ii = blockIdx.x * 128 + ty * 8 + i;
#pragma unroll
        for (int j = 0; j < 8; j++) {
            int jj = blockIdx.y * 128 + tx * 8 + j;
            float val = acc[i][j] * scale;
            if (mask[b * SS + jj]) val = -1e9f;
            outp[(size_t)ii * SS + jj] = val;
        }
    }
}

// ---------------------------------------------------------------------------
// K5: row softmax over 1024 scores. 256 threads, 4 elements each (float4).
// ---------------------------------------------------------------------------
__global__ __launch_bounds__(256)
void softmax_kernel()
{
    const size_t row = blockIdx.x;
    float4* p = (float4*)(g_sc + row * SS);
    float4 vv = p[threadIdx.x];

    float m = fmaxf(fmaxf(vv.x, vv.y), fmaxf(vv.z, vv.w));
    const int lane = threadIdx.x & 31, wid = threadIdx.x >> 5;
#pragma unroll
    for (int off = 16; off; off >>= 1)
        m = fmaxf(m, __shfl_xor_sync(0xFFFFFFFFu, m, off));
    __shared__ float sm[8];
    if (lane == 0) sm[wid] = m;
    __syncthreads();
    m = sm[0];
#pragma unroll
    for (int w = 1; w < 8; w++) m = fmaxf(m, sm[w]);

    float4 e;
    e.x = __expf(vv.x - m); e.y = __expf(vv.y - m);
    e.z = __expf(vv.z - m); e.w = __expf(vv.w - m);
    float s = e.x + e.y + e.z + e.w;
#pragma unroll
    for (int off = 16; off; off >>= 1)
        s += __shfl_xor_sync(0xFFFFFFFFu, s, off);
    __shared__ float ss[8];
    if (lane == 0) ss[wid] = s;
    __syncthreads();
    s = ss[0] + ss[1] + ss[2] + ss[3] + ss[4] + ss[5] + ss[6] + ss[7];
    float inv = 1.0f / s;
    e.x *= inv; e.y *= inv; e.z *= inv; e.w *= inv;
    p[threadIdx.x] = e;
}

// ---------------------------------------------------------------------------
// K6: ctx = att @ vh, written into merged-head layout [b*s, h*128+d].
// grid (8, 1, 64).
// ---------------------------------------------------------------------------
__global__ __launch_bounds__(256)
void out_kernel()
{
    __shared__ float As[16][132];
    __shared__ float Bs[16][132];
    float acc[8][8] = {};

    const int bh = blockIdx.z;
    const int m0 = blockIdx.x * 128;
    const float* A  = g_sc + (size_t)bh * SS * SS + (size_t)m0 * SS;
    const float* Bp = g_vh + (size_t)bh * SS * DB;

    gemm_128x128<false>(A, SS, Bp, DB, SS, As, Bs, acc);

    const int ty = threadIdx.x >> 4, tx = threadIdx.x & 15;
    const int b = bh >> 3, h = bh & 7;
#pragma unroll
    for (int i = 0; i < 8; i++) {
        int s = m0 + ty * 8 + i;
#pragma unroll
        for (int j = 0; j < 8; j++) {
            int d = tx * 8 + j;
            g_ctx[((size_t)(b * SS + s)) * DD + h * DB + d] = acc[i][j];
        }
    }
}

// ---------------------------------------------------------------------------
// K7: final projection: out = ctx @ Wm + bm. grid (64, 8).
// ---------------------------------------------------------------------------
__global__ __launch_bounds__(256)
void final_kernel(const float* __restrict__ Wm, const float* __restrict__ bm,
                  float* __restrict__ outp)
{
    __shared__ float As[16][132];
    __shared__ float Bs[16][132];
    float acc[8][8] = {};

    const int m0 = blockIdx.x * 128;
    const int n0 = blockIdx.y * 128;
    gemm_128x128<false>(g_ctx + (size_t)m0 * DD, DD, Wm + n0, DD, DD, As, Bs, acc);

    const int ty = threadIdx.x >> 4, tx = threadIdx.x & 15;
#pragma unroll
    for (int i = 0; i < 8; i++) {
        int m = m0 + ty * 8 + i;
#pragma unroll
        for (int j = 0; j < 8; j++) {
            int n = n0 + tx * 8 + j;
            outp[(size_t)m * DD + n] = acc[i][j] + bm[n];
        }
    }
}

// ---------------------------------------------------------------------------
extern "C" void kernel_launch(void* const* d_in, const int* in_sizes, int n_in,
                              void* d_out, int out_size)
{
    (void)in_sizes; (void)n_in; (void)out_size;
    const float* v  = (const float*)d_in[0];
    const float* k  = (const float*)d_in[1];
    const float* q  = (const float*)d_in[2];
    const unsigned char* mask = (const unsigned char*)d_in[3];
    const float* Wv = (const float*)d_in[4];
    const float* bv = (const float*)d_in[5];
    const float* Wk = (const float*)d_in[6];
    const float* bk = (const float*)d_in[7];
    const float* Wq = (const float*)d_in[8];
    const float* bq = (const float*)d_in[9];
    const float* Wm = (const float*)d_in[10];
    const float* bm = (const float*)d_in[11];
    const float* WgX = (const float*)d_in[12];
    const float* bgX = (const float*)d_in[13];
    const float* WgY = (const float*)d_in[14];
    const float* bgY = (const float*)d_in[15];
    const float* Wg2 = (const float*)d_in[16];
    const float* bg2 = (const float*)d_in[17];
    float* outp = (float*)d_out;

    proj_kernel<<<dim3(64, 8, 3), 256>>>(v, k, q, Wv, bv, Wk, bk, Wq, bq);
    gate_gemm_kernel<<<dim3(8, 2, 64), 256>>>(WgX, bgX, WgY, bgY);
    gate_apply_kernel<<<BH * SS, 128>>>(Wg2, bg2);
    scores_kernel<<<dim3(8, 8, 64), 256>>>(mask);
    softmax_kernel<<<BH * SS, 256>>>();
    out_kernel<<<dim3(8, 1, 64), 256>>>();
    final_kernel<<<dim3(64, 8), 256>>>(Wm, bm, outp);
}

// round 5
// speedup vs baseline: 1.7194x; 1.7189x over previous
#include <cuda_runtime.h>
#include <cuda_bf16.h>
#include <cstdint>
#include <math.h>

#define SSZ 1024
#define HSZ 8
#define BHZ 64
#define MT  8192
typedef __nv_bfloat16 bf;

// ---------------- scratch (device globals) ----------------
__device__ __align__(16) bf    g_xc[3][(size_t)MT * 3072];      // split acts (hi,hi,lo)
__device__ __align__(16) bf    g_wc[4][(size_t)1024 * 3072];    // W^T split (hi,lo,hi): v,k,q,m
__device__ __align__(16) bf    g_wgc[2][(size_t)128 * 384];     // WgX^T, WgY^T split (hi,lo,hi)
__device__ __align__(16) float g_kh[(size_t)BHZ * SSZ * 128];
__device__ __align__(16) float g_qh[(size_t)BHZ * SSZ * 128];
__device__ __align__(16) bf    g_khc[(size_t)BHZ * SSZ * 384];  // (hi,hi,lo)
__device__ __align__(16) bf    g_qhc[(size_t)BHZ * SSZ * 384];
__device__ __align__(16) float g_gx[(size_t)BHZ * SSZ * 128];
__device__ __align__(16) float g_gy[(size_t)BHZ * SSZ * 128];
__device__ __align__(16) bf    g_kgc[(size_t)BHZ * SSZ * 384];  // gated k (hi,lo,hi)  [B side]
__device__ __align__(16) bf    g_qgc[(size_t)BHZ * SSZ * 384];  // gated q (hi,hi,lo)  [A side]
__device__ __align__(16) bf    g_vtc[(size_t)BHZ * 128 * 3072]; // v^T per head (hi,lo,hi)
__device__ __align__(16) float g_sc[(size_t)BHZ * SSZ * SSZ];
__device__ __align__(16) bf    g_attc[(size_t)BHZ * SSZ * 3072];// att (hi,hi,lo)
__device__ __align__(16) bf    g_ctxc[(size_t)MT * 3072];       // ctx (hi,hi,lo)

// ---------------- helpers ----------------
__device__ __forceinline__ uint32_t smem_u32(const void* p) {
    uint32_t a;
    asm("{ .reg .u64 t; cvta.to.shared.u64 t, %1; cvt.u32.u64 %0, t; }" : "=r"(a) : "l"(p));
    return a;
}
__device__ __forceinline__ uint32_t sw128(uint32_t o) { return o ^ ((o >> 3) & 0x70); }
__device__ __forceinline__ void split_bf(float v, bf& hi, bf& lo) {
    hi = __float2bfloat16(v);
    lo = __float2bfloat16(v - __bfloat162float(hi));
}

// ---------------- mma.sync GEMM: C(128x128)=A[m][K']*B[n][K']^T ----------------
struct GArgs {
    const bf *A, *B;
    long lda, ldb, bsA, bsB;
    int K;
    const float* bias;
    const unsigned char* mask;
    float* of;
    bf* oc;
};

// MODE: 0=projV(transposed split) 1=projKQ(f32+split) 2=gate(f32) 3=scores 4=attV(split) 5=final
template<int MODE>
__global__ __launch_bounds__(256) void tc_gemm(GArgs g)
{
    extern __shared__ __align__(16) char smt[];
    const uint32_t smbase = smem_u32(smt);
    const int t = threadIdx.x;
    const int lane = t & 31, wid = t >> 5;
    const int warp_m = wid >> 2, warp_n = wid & 3;

    const int m0 = blockIdx.x * 128;
    const int n0 = blockIdx.y * 128;
    const int bz = blockIdx.z;
    const bf* Ab = g.A + (size_t)bz * g.bsA + (size_t)m0 * g.lda;
    const bf* Bb = g.B + (size_t)bz * g.bsB + (size_t)n0 * g.ldb;

    float acc[4][4][4];
#pragma unroll
    for (int i = 0; i < 4; i++)
#pragma unroll
        for (int j = 0; j < 4; j++)
#pragma unroll
            for (int c = 0; c < 4; c++) acc[i][j][c] = 0.f;

    const int nch = g.K >> 6;

    // precomputed smem load addresses for ldmatrix
    const uint32_t aoff = sw128((warp_m * 64 + (lane & 15)) * 128 + (lane >> 4) * 16);
    const uint32_t boff = sw128((warp_n * 32 + ((lane >> 4) & 1) * 8 + (lane & 7)) * 128
                                + ((lane >> 3) & 1) * 16);

#define PREFETCH(i)                                                              \
    {                                                                            \
        const bf* Ap = Ab + (i) * 64;                                            \
        const bf* Bp = Bb + (i) * 64;                                            \
        const uint32_t sA = smbase + ((i) & 1) * 32768;                          \
        const uint32_t sB = sA + 16384;                                          \
        _Pragma("unroll")                                                        \
        for (int r = 0; r < 4; r++) {                                            \
            const int it = t + r * 256;                                          \
            const int row = it >> 3, seg = it & 7;                               \
            const uint32_t da = sA + sw128(row * 128 + seg * 16);                \
            const bf* pa = Ap + (size_t)row * g.lda + seg * 8;                   \
            asm volatile("cp.async.cg.shared.global [%0], [%1], 16;" :: "r"(da), "l"(pa)); \
            const uint32_t db = sB + sw128(row * 128 + seg * 16);                \
            const bf* pb = Bp + (size_t)row * g.ldb + seg * 8;                   \
            asm volatile("cp.async.cg.shared.global [%0], [%1], 16;" :: "r"(db), "l"(pb)); \
        }                                                                        \
    }

    PREFETCH(0);
    asm volatile("cp.async.commit_group;" ::: "memory");
    if (nch > 1) PREFETCH(1);
    asm volatile("cp.async.commit_group;" ::: "memory");

    for (int i = 0; i < nch; i++) {
        asm volatile("cp.async.wait_group 1;" ::: "memory");
        __syncthreads();
        const uint32_t sA = smbase + (i & 1) * 32768;
        const uint32_t sB = sA + 16384;
#pragma unroll
        for (int ks = 0; ks < 4; ks++) {
            const int kb = ks * 32;   // byte offset of this k16 within the 128B row
            uint32_t a[4][4], b[4][2];
#pragma unroll
            for (int mi = 0; mi < 4; mi++) {
                // sw128 XOR only touches bits[6:4]; kb (bits>=5) changes them, so recompute
                const uint32_t addr = sA + sw128((warp_m * 64 + mi * 16 + (lane & 15)) * 128
                                                 + kb + (lane >> 4) * 16);
                asm volatile("ldmatrix.sync.aligned.m8n8.x4.shared.b16 {%0,%1,%2,%3}, [%4];"
                    : "=r"(a[mi][0]), "=r"(a[mi][1]), "=r"(a[mi][2]), "=r"(a[mi][3]) : "r"(addr));
            }
#pragma unroll
            for (int jp = 0; jp < 2; jp++) {
                const uint32_t addr = sB + sw128((warp_n * 32 + jp * 16 + ((lane >> 4) & 1) * 8
                                                  + (lane & 7)) * 128
                                                 + kb + ((lane >> 3) & 1) * 16);
                asm volatile("ldmatrix.sync.aligned.m8n8.x4.shared.b16 {%0,%1,%2,%3}, [%4];"
                    : "=r"(b[jp * 2][0]), "=r"(b[jp * 2][1]),
                      "=r"(b[jp * 2 + 1][0]), "=r"(b[jp * 2 + 1][1]) : "r"(addr));
            }
#pragma unroll
            for (int mi = 0; mi < 4; mi++)
#pragma unroll
                for (int nj = 0; nj < 4; nj++)
                    asm volatile(
                        "mma.sync.aligned.m16n8k16.row.col.f32.bf16.bf16.f32 "
                        "{%0,%1,%2,%3}, {%4,%5,%6,%7}, {%8,%9}, {%0,%1,%2,%3};"
                        : "+f"(acc[mi][nj][0]), "+f"(acc[mi][nj][1]),
                          "+f"(acc[mi][nj][2]), "+f"(acc[mi][nj][3])
                        : "r"(a[mi][0]), "r"(a[mi][1]), "r"(a[mi][2]), "r"(a[mi][3]),
                          "r"(b[nj][0]), "r"(b[nj][1]));
        }
        __syncthreads();
        if (i + 2 < nch) PREFETCH(i + 2);
        asm volatile("cp.async.commit_group;" ::: "memory");
    }
    asm volatile("cp.async.wait_group 0;" ::: "memory");
    (void)aoff; (void)boff;

    // ---------------- epilogue: 4 col-blocks of 32 through smem staging ----------------
    float* stg = (float*)smt;   // 128 x 33 fp32
    for (int cb = 0; cb < 4; cb++) {
        __syncthreads();
        if (warp_n == cb) {
#pragma unroll
            for (int mi = 0; mi < 4; mi++)
#pragma unroll
                for (int nj = 0; nj < 4; nj++) {
                    const int r  = warp_m * 64 + mi * 16 + (lane >> 2);
                    const int cc = nj * 8 + (lane & 3) * 2;
                    stg[r * 33 + cc]           = acc[mi][nj][0];
                    stg[r * 33 + cc + 1]       = acc[mi][nj][1];
                    stg[(r + 8) * 33 + cc]     = acc[mi][nj][2];
                    stg[(r + 8) * 33 + cc + 1] = acc[mi][nj][3];
                }
        }
        __syncthreads();

        if (MODE == 0) {
            // v^T: per-head [bh][d][3S] (hi,lo,hi)
            const int dloc = t & 31, soff = (t >> 5) * 16;
            const int b = m0 >> 10, h = blockIdx.y, d = cb * 32 + dloc;
            const int scol = (m0 & 1023) + soff;
            bf hi16[16], lo16[16];
#pragma unroll
            for (int i2 = 0; i2 < 16; i2++) {
                float v = stg[(soff + i2) * 33 + dloc] + g.bias[n0 + d];
                split_bf(v, hi16[i2], lo16[i2]);
            }
            bf* dst = g.oc + ((size_t)(b * HSZ + h) * 128 + d) * 3072 + scol;
            uint4* hv = (uint4*)hi16; uint4* lv = (uint4*)lo16;
            *(uint4*)(dst) = hv[0];          *(uint4*)(dst + 8) = hv[1];
            *(uint4*)(dst + 1024) = lv[0];   *(uint4*)(dst + 1032) = lv[1];
            *(uint4*)(dst + 2048) = hv[0];   *(uint4*)(dst + 2056) = hv[1];
        } else {
            const int row = t >> 1, c0 = (t & 1) * 16;
            const float* sr = stg + row * 33 + c0;
            if (MODE == 1) {
                const int h = blockIdx.y, m = m0 + row, b = m >> 10, s = m & 1023;
                const int d0 = cb * 32 + c0;
                const size_t ri = (size_t)(b * HSZ + h) * SSZ + s;
                float* fd = g.of + ri * 128 + d0;
                bf* cd = g.oc + ri * 384 + d0;
#pragma unroll
                for (int c = 0; c < 16; c++) {
                    float v = sr[c] + g.bias[n0 + d0 + c];
                    fd[c] = v;
                    bf hi, lo; split_bf(v, hi, lo);
                    cd[c] = hi; cd[128 + c] = hi; cd[256 + c] = lo;
                }
            } else if (MODE == 2) {
                float* fd = g.of + (size_t)(m0 + row) * 128 + cb * 32 + c0;
#pragma unroll
                for (int c = 0; c < 16; c += 4) {
                    float4 w;
                    w.x = sr[c]     + g.bias[cb * 32 + c0 + c];
                    w.y = sr[c + 1] + g.bias[cb * 32 + c0 + c + 1];
                    w.z = sr[c + 2] + g.bias[cb * 32 + c0 + c + 2];
                    w.w = sr[c + 3] + g.bias[cb * 32 + c0 + c + 3];
                    *(float4*)(fd + c) = w;
                }
            } else if (MODE == 3) {
                const int nt = n0 + cb * 32 + c0;
                float* fd = g.of + ((size_t)bz * SSZ + m0 + row) * SSZ + nt;
                const unsigned char* mk = g.mask + (size_t)(bz >> 3) * SSZ + nt;
                const float sc = 0.08838834764831845f;
#pragma unroll
                for (int c = 0; c < 16; c += 4) {
                    float4 w;
                    w.x = mk[c]     ? -1e9f : sr[c]     * sc;
                    w.y = mk[c + 1] ? -1e9f : sr[c + 1] * sc;
                    w.z = mk[c + 2] ? -1e9f : sr[c + 2] * sc;
                    w.w = mk[c + 3] ? -1e9f : sr[c + 3] * sc;
                    *(float4*)(fd + c) = w;
                }
            } else if (MODE == 4) {
                const int b = bz >> 3, h = bz & 7, n = cb * 32 + c0;
                bf* cd = g.oc + ((size_t)b * SSZ + m0 + row) * 3072 + h * 128 + n;
                bf hi16[16], lo16[16];
#pragma unroll
                for (int c = 0; c < 16; c++) split_bf(sr[c], hi16[c], lo16[c]);
                uint4* hv = (uint4*)hi16; uint4* lv = (uint4*)lo16;
                *(uint4*)(cd) = hv[0];          *(uint4*)(cd + 8) = hv[1];
                *(uint4*)(cd + 1024) = hv[0];   *(uint4*)(cd + 1032) = hv[1];
                *(uint4*)(cd + 2048) = lv[0];   *(uint4*)(cd + 2056) = lv[1];
            } else {
                const int nt = n0 + cb * 32 + c0;
                float* fd = g.of + (size_t)(m0 + row) * 1024 + nt;
#pragma unroll
                for (int c = 0; c < 16; c += 4) {
                    float4 w;
                    w.x = sr[c]     + g.bias[nt + c];
                    w.y = sr[c + 1] + g.bias[nt + c + 1];
                    w.z = sr[c + 2] + g.bias[nt + c + 2];
                    w.w = sr[c + 3] + g.bias[nt + c + 3];
                    *(float4*)(fd + c) = w;
                }
            }
        }
    }
}

// ---------------- prep kernels ----------------
__global__ __launch_bounds__(256) void split_act(const float* v, const float* k, const float* q)
{
    const float* s = blockIdx.z == 0 ? v : blockIdx.z == 1 ? k : q;
    bf* dst = g_xc[blockIdx.z];
    const size_t i = ((size_t)blockIdx.x * 256 + threadIdx.x) * 4;
    const size_t row = i >> 10, col = i & 1023;
    float4 x = *(const float4*)(s + i);
    bf h[4], l[4];
    split_bf(x.x, h[0], l[0]); split_bf(x.y, h[1], l[1]);
    split_bf(x.z, h[2], l[2]); split_bf(x.w, h[3], l[3]);
    bf* d = dst + row * 3072 + col;
    *(uint2*)(d) = *(uint2*)h;
    *(uint2*)(d + 1024) = *(uint2*)h;
    *(uint2*)(d + 2048) = *(uint2*)l;
}

__global__ void wsplit(const float* W, bf* Wc, int K, int N)
{
    __shared__ float sm[32][33];
    const int k0 = blockIdx.y * 32, n0 = blockIdx.x * 32;
    for (int r = threadIdx.y; r < 32; r += 8)
        sm[r][threadIdx.x] = W[(size_t)(k0 + r) * N + n0 + threadIdx.x];
    __syncthreads();
    for (int r = threadIdx.y; r < 32; r += 8) {
        bf hi, lo; split_bf(sm[threadIdx.x][r], hi, lo);
        bf* d = Wc + (size_t)(n0 + r) * 3 * K + k0 + threadIdx.x;
        d[0] = hi; d[K] = lo; d[2 * K] = hi;
    }
}

__global__ __launch_bounds__(128) void gate_apply(const float* Wg2, const float* bg2)
{
    const size_t row = blockIdx.x;
    const int d = threadIdx.x;
    const size_t o = row * 128 + d;
    float tv = g_gx[o] * g_gy[o];
    float s0 = tv * Wg2[d * 2], s1 = tv * Wg2[d * 2 + 1];
    const int lane = d & 31, w = d >> 5;
#pragma unroll
    for (int off = 16; off; off >>= 1) {
        s0 += __shfl_xor_sync(0xFFFFFFFFu, s0, off);
        s1 += __shfl_xor_sync(0xFFFFFFFFu, s1, off);
    }
    __shared__ float r0[4], r1[4];
    if (lane == 0) { r0[w] = s0; r1[w] = s1; }
    __syncthreads();
    float t0 = r0[0] + r0[1] + r0[2] + r0[3];
    float t1 = r1[0] + r1[1] + r1[2] + r1[3];
    float gk = 1.f / (1.f + __expf(-(t0 + bg2[0])));
    float gq = 1.f / (1.f + __expf(-(t1 + bg2[1])));
    bf hi, lo;
    split_bf(g_kh[o] * gk, hi, lo);
    bf* kd = g_kgc + row * 384 + d;                       // (hi,lo,hi)
    kd[0] = hi; kd[128] = lo; kd[256] = hi;
    split_bf(g_qh[o] * gq, hi, lo);
    bf* qd = g_qgc + row * 384 + d;                       // (hi,hi,lo)
    qd[0] = hi; qd[128] = hi; qd[256] = lo;
}

__global__ __launch_bounds__(256) void softmax_kernel()
{
    const size_t row = blockIdx.x;
    const float4 vv = *(const float4*)(g_sc + row * SSZ + threadIdx.x * 4);
    float m = fmaxf(fmaxf(vv.x, vv.y), fmaxf(vv.z, vv.w));
    const int lane = threadIdx.x & 31, w = threadIdx.x >> 5;
#pragma unroll
    for (int off = 16; off; off >>= 1) m = fmaxf(m, __shfl_xor_sync(0xFFFFFFFFu, m, off));
    __shared__ float sm[8], ssum[8];
    if (lane == 0) sm[w] = m;
    __syncthreads();
    m = sm[0];
#pragma unroll
    for (int i = 1; i < 8; i++) m = fmaxf(m, sm[i]);
    float4 e;
    e.x = __expf(vv.x - m); e.y = __expf(vv.y - m);
    e.z = __expf(vv.z - m); e.w = __expf(vv.w - m);
    float s = e.x + e.y + e.z + e.w;
#pragma unroll
    for (int off = 16; off; off >>= 1) s += __shfl_xor_sync(0xFFFFFFFFu, s, off);
    if (lane == 0) ssum[w] = s;
    __syncthreads();
    s = ssum[0] + ssum[1] + ssum[2] + ssum[3] + ssum[4] + ssum[5] + ssum[6] + ssum[7];
    const float inv = 1.f / s;
    bf h[4], l[4];
    split_bf(e.x * inv, h[0], l[0]); split_bf(e.y * inv, h[1], l[1]);
    split_bf(e.z * inv, h[2], l[2]); split_bf(e.w * inv, h[3], l[3]);
    bf* d = g_attc + row * 3072 + threadIdx.x * 4;        // (hi,hi,lo)
    *(uint2*)(d) = *(uint2*)h;
    *(uint2*)(d + 1024) = *(uint2*)h;
    *(uint2*)(d + 2048) = *(uint2*)l;
}

// ---------------- launch ----------------
#define TCSMEM 65536

extern "C" void kernel_launch(void* const* d_in, const int* in_sizes, int n_in,
                              void* d_out, int out_size)
{
    (void)in_sizes; (void)n_in; (void)out_size;
    const float* v  = (const float*)d_in[0];
    const float* k  = (const float*)d_in[1];
    const float* q  = (const float*)d_in[2];
    const unsigned char* mask = (const unsigned char*)d_in[3];
    const float* Wv = (const float*)d_in[4];  const float* bv = (const float*)d_in[5];
    const float* Wk = (const float*)d_in[6];  const float* bk = (const float*)d_in[7];
    const float* Wq = (const float*)d_in[8];  const float* bq = (const float*)d_in[9];
    const float* Wm = (const float*)d_in[10]; const float* bm = (const float*)d_in[11];
    const float* WgX = (const float*)d_in[12]; const float* bgX = (const float*)d_in[13];
    const float* WgY = (const float*)d_in[14]; const float* bgY = (const float*)d_in[15];
    const float* Wg2 = (const float*)d_in[16]; const float* bg2 = (const float*)d_in[17];
    float* outp = (float*)d_out;

    cudaFuncSetAttribute(tc_gemm<0>, cudaFuncAttributeMaxDynamicSharedMemorySize, TCSMEM);
    cudaFuncSetAttribute(tc_gemm<1>, cudaFuncAttributeMaxDynamicSharedMemorySize, TCSMEM);
    cudaFuncSetAttribute(tc_gemm<2>, cudaFuncAttributeMaxDynamicSharedMemorySize, TCSMEM);
    cudaFuncSetAttribute(tc_gemm<3>, cudaFuncAttributeMaxDynamicSharedMemorySize, TCSMEM);
    cudaFuncSetAttribute(tc_gemm<4>, cudaFuncAttributeMaxDynamicSharedMemorySize, TCSMEM);
    cudaFuncSetAttribute(tc_gemm<5>, cudaFuncAttributeMaxDynamicSharedMemorySize, TCSMEM);

    bf* wc0; bf* wc1; bf* wc2; bf* wc3; bf* wg0; bf* wg1;
    bf* xc0; bf* xc1; bf* xc2;
    cudaGetSymbolAddress((void**)&wc0, g_wc);  wc1 = wc0 + (size_t)1024 * 3072;
    wc2 = wc1 + (size_t)1024 * 3072; wc3 = wc2 + (size_t)1024 * 3072;
    cudaGetSymbolAddress((void**)&wg0, g_wgc); wg1 = wg0 + (size_t)128 * 384;
    cudaGetSymbolAddress((void**)&xc0, g_xc);  xc1 = xc0 + (size_t)MT * 3072; xc2 = xc1 + (size_t)MT * 3072;
    float *kh, *qh, *gx, *gy, *sc;
    bf *khc, *qhc, *kgc, *qgc, *vtc, *attc, *ctxc;
    cudaGetSymbolAddress((void**)&kh, g_kh);   cudaGetSymbolAddress((void**)&qh, g_qh);
    cudaGetSymbolAddress((void**)&gx, g_gx);   cudaGetSymbolAddress((void**)&gy, g_gy);
    cudaGetSymbolAddress((void**)&sc, g_sc);
    cudaGetSymbolAddress((void**)&khc, g_khc); cudaGetSymbolAddress((void**)&qhc, g_qhc);
    cudaGetSymbolAddress((void**)&kgc, g_kgc); cudaGetSymbolAddress((void**)&qgc, g_qgc);
    cudaGetSymbolAddress((void**)&vtc, g_vtc); cudaGetSymbolAddress((void**)&attc, g_attc);
    cudaGetSymbolAddress((void**)&ctxc, g_ctxc);

    split_act<<<dim3(8192, 1, 3), 256>>>(v, k, q);
    wsplit<<<dim3(32, 32), dim3(32, 8)>>>(Wv, wc0, 1024, 1024);
    wsplit<<<dim3(32, 32), dim3(32, 8)>>>(Wk, wc1, 1024, 1024);
    wsplit<<<dim3(32, 32), dim3(32, 8)>>>(Wq, wc2, 1024, 1024);
    wsplit<<<dim3(32, 32), dim3(32, 8)>>>(Wm, wc3, 1024, 1024);
    wsplit<<<dim3(4, 4),   dim3(32, 8)>>>(WgX, wg0, 128, 128);
    wsplit<<<dim3(4, 4),   dim3(32, 8)>>>(WgY, wg1, 128, 128);

    GArgs a = {};
    // proj V -> vtc
    a.A = xc0; a.B = wc0; a.lda = 3072; a.ldb = 3072; a.bsA = 0; a.bsB = 0;
    a.K = 3072; a.bias = bv; a.oc = vtc;
    tc_gemm<0><<<dim3(64, 8, 1), 256, TCSMEM>>>(a);
    // proj K -> kh + khc
    a.B = wc1; a.bias = bk; a.of = kh; a.oc = khc; a.A = xc1;
    tc_gemm<1><<<dim3(64, 8, 1), 256, TCSMEM>>>(a);
    // proj Q -> qh + qhc
    a.B = wc2; a.bias = bq; a.of = qh; a.oc = qhc; a.A = xc2;
    tc_gemm<1><<<dim3(64, 8, 1), 256, TCSMEM>>>(a);
    // gate X / Y
    a.A = khc; a.B = wg0; a.lda = 384; a.ldb = 384; a.K = 384; a.bias = bgX; a.of = gx; a.oc = nullptr;
    tc_gemm<2><<<dim3(512, 1, 1), 256, TCSMEM>>>(a);
    a.A = qhc; a.B = wg1; a.bias = bgY; a.of = gy;
    tc_gemm<2><<<dim3(512, 1, 1), 256, TCSMEM>>>(a);

    gate_apply<<<BHZ * SSZ, 128>>>(Wg2, bg2);

    // scores
    a.A = qgc; a.B = kgc; a.lda = 384; a.ldb = 384; a.bsA = (long)SSZ * 384; a.bsB = (long)SSZ * 384;
    a.K = 384; a.mask = mask; a.of = sc; a.bias = nullptr;
    tc_gemm<3><<<dim3(8, 8, BHZ), 256, TCSMEM>>>(a);

    softmax_kernel<<<BHZ * SSZ, 256>>>();

    // attV -> ctxc
    a.A = attc; a.B = vtc; a.lda = 3072; a.ldb = 3072;
    a.bsA = (long)SSZ * 3072; a.bsB = (long)128 * 3072;
    a.K = 3072; a.mask = nullptr; a.of = nullptr; a.oc = ctxc;
    tc_gemm<4><<<dim3(8, 1, BHZ), 256, TCSMEM>>>(a);

    // final
    a.A = ctxc; a.B = wc3; a.bsA = 0; a.bsB = 0; a.bias = bm; a.of = outp; a.oc = nullptr;
    tc_gemm<5><<<dim3(64, 8, 1), 256, TCSMEM>>>(a);
}